// round 7
// baseline (speedup 1.0000x reference)
#include <cuda_runtime.h>
#include <math.h>

#define BB 256
#define TT 512
#define KK 128

// Scratch (allocation-free rule: __device__ globals).
__device__ unsigned char g_bp[(size_t)BB * TT * KK];   // backpointers, 16.8 MB
__device__ float g_nll[BB];

// smem layout (bytes):
//   [0, 67584)        s_mat : Viterbi = trans row-major (64KB, reused as bp cache)
//                             LSE     = exp(trans) transposed, rows padded to 132 floats
//   [67584, 71680)    s_p   : LSE p vectors, [2 buf][4 batch][128] floats (4KB)
//   [71680, 71712)    s_M   : [2 buf][4] stale M
//   [71712, 73760)    s_cand: 4 warps x 32 uint2 (+ prologue len cache)
//   [73760, 73792)    s_cnt : 8 ints
//   [73792, 73808)    s_wkey: 4 u32
//   [73808, 73936)    s_red : 16 floats + 16 ints
//   [73936, 74960)    s_ord : 256 ints (descending-length order)
#define OFF_P    67584
#define OFF_M    71680
#define OFF_CAND 71712
#define OFF_CNT  73760
#define OFF_WKEY 73792
#define OFF_RED  73808
#define OFF_ORD  73936
#define SMEM_BYTES 74960

#define FMA2(acc, a, b) asm("fma.rn.f32x2 %0, %1, %2, %0;" : "+l"(acc) : "l"(a), "l"(b))
#define ADD2(d, a, b)   asm("add.rn.f32x2 %0, %1, %2;" : "=l"(d) : "l"(a), "l"(b))

// order-preserving float<->uint key (no NaNs in this data)
__device__ __forceinline__ unsigned fkey(float f) {
    unsigned u = __float_as_uint(f);
    return (u & 0x80000000u) ? ~u : (u | 0x80000000u);
}
__device__ __forceinline__ float fval(unsigned k) {
    return __uint_as_float((k & 0x80000000u) ? (k & 0x7FFFFFFFu) : ~k);
}

extern "C" __global__ void __launch_bounds__(128, 3) crf_fwd(
    const float* __restrict__ logits,
    const int*   __restrict__ labels,
    const int*   __restrict__ seq_lens,
    const float* __restrict__ trans,
    float* __restrict__ out)
{
    extern __shared__ char smem_raw[];
    float*    s_mat  = (float*)smem_raw;
    float*    s_p    = (float*)(smem_raw + OFF_P);
    float*    s_M    = (float*)(smem_raw + OFF_M);
    uint2*    s_cand = (uint2*)(smem_raw + OFF_CAND);
    int*      s_cnt  = (int*)(smem_raw + OFF_CNT);
    unsigned* s_wkey = (unsigned*)(smem_raw + OFF_WKEY);
    float*    s_red  = (float*)(smem_raw + OFF_RED);
    int*      s_redi = (int*)(s_red + 16);
    int*      s_ord  = (int*)(smem_raw + OFF_ORD);

    const int tid  = threadIdx.x;
    const int lane = tid & 31;
    const int wid  = tid >> 5;

    // ----- prologue: rank batches by descending length -----
    {
        int* s_len = (int*)(smem_raw + OFF_CAND);     // reuse cand region
        for (int bt = tid; bt < BB; bt += 128) s_len[bt] = __ldg(&seq_lens[bt]);
        __syncthreads();
        for (int bt = tid; bt < BB; bt += 128) {
            int my = s_len[bt];
            int r = 0;
            #pragma unroll 8
            for (int jb = 0; jb < BB; ++jb) {
                int lj = s_len[jb];
                r += (lj > my) || (lj == my && jb < bt);
            }
            s_ord[r] = bt;
        }
        __syncthreads();
    }

    // grid 320: bid < 64 -> LSE CTA over ranks 4g..4g+3; else Viterbi CTA over rank bid-64
    const bool is_lse = (blockIdx.x < 64);

    if (!is_lse) {
        // ========== Viterbi: global-threshold exact pruning (R4-proven) ==========
        const int b   = s_ord[blockIdx.x - 64];
        const int len = seq_lens[b];
        const float* lgb = logits + (size_t)b * TT * KK;

        for (int idx = tid; idx < KK * KK; idx += 128) s_mat[idx] = trans[idx];
        float alpha = lgb[tid];
        __syncthreads();

        unsigned char* bp_out = &g_bp[(size_t)b * TT * KK];
        float e_cur = (len > 1) ? __ldg(&lgb[KK + tid]) : 0.f;
        for (int t = 1; t < len; ++t) {
            int tn = (t + 1 < len) ? t + 1 : t;
            float e_next = __ldg(&lgb[tn * KK + tid]);      // prefetch next emission
            unsigned wk = __reduce_max_sync(0xFFFFFFFFu, fkey(alpha));
            if (lane == 0) s_wkey[wid] = wk;
            __syncthreads();
            unsigned ak = max(max(s_wkey[0], s_wkey[1]), max(s_wkey[2], s_wkey[3]));
            float amax = fval(ak);
            // trans in [0,1): alpha <= amax-1 dominated; margin >> ulp(|alpha|).
            bool keep = alpha >= amax - 1.002f;
            unsigned mask = __ballot_sync(0xFFFFFFFFu, keep);
            if (keep) {
                int pos = __popc(mask & ((1u << lane) - 1u));
                s_cand[wid * 32 + pos] = make_uint2(__float_as_uint(alpha), (unsigned)tid);
            }
            if (lane == 0) s_cnt[wid] = __popc(mask);
            __syncthreads();
            float best = -INFINITY; int bi = 0;
            #pragma unroll 1
            for (int w = 0; w < 4; ++w) {
                int cnt = s_cnt[w];
                const uint2* lst = &s_cand[w * 32];
                for (int c = 0; c < cnt; ++c) {      // ascending i: strict > keeps first argmax
                    uint2 e = lst[c];
                    float s = __uint_as_float(e.x) + s_mat[e.y * KK + tid];
                    if (s > best) { best = s; bi = (int)e.y; }
                }
            }
            alpha = best + e_cur;
            e_cur = e_next;
            bp_out[t * KK + tid] = (unsigned char)bi;
        }
        // final argmax, first-index tie break
        {
            float bv = alpha; int bidx = tid;
            #pragma unroll
            for (int m = 16; m > 0; m >>= 1) {
                float ov = __shfl_xor_sync(0xFFFFFFFFu, bv, m);
                int   oi = __shfl_xor_sync(0xFFFFFFFFu, bidx, m);
                if (ov > bv || (ov == bv && oi < bidx)) { bv = ov; bidx = oi; }
            }
            if (lane == 0) { s_red[wid] = bv; s_redi[wid] = bidx; }
        }
        __syncthreads();
        int last;
        {
            float bv = s_red[0]; int bidx = s_redi[0];
            #pragma unroll
            for (int w = 1; w < 4; ++w) {
                float wv = s_red[w]; int wi = s_redi[w];
                if (wv > bv || (wv == bv && wi < bidx)) { bv = wv; bidx = wi; }
            }
            last = bidx;
        }
        __syncthreads();   // done with s_mat -> reuse as bp cache

        unsigned char* s_bp = (unsigned char*)s_mat;
        {
            const int nbytes = (len - 1) * KK;        // multiple of 16, <= 65408
            const int4* src = (const int4*)&g_bp[((size_t)b * TT + 1) * KK];
            int4* dst = (int4*)s_bp;
            for (int i = tid; i * 16 < nbytes; i += 128) dst[i] = src[i];
        }
        __syncthreads();
        if (tid == 0) {
            float* pred = out + 1 + (size_t)b * TT;
            int tag = last;
            for (int t = TT - 1; t >= len - 1; --t) pred[t] = (float)tag;
            for (int t = len - 1; t >= 1; --t) {
                tag = s_bp[(t - 1) * KK + tag];
                pred[t - 1] = (float)tag;
            }
        }
    } else {
        // ========== LSE: 4 batches/CTA, FFMA2 matvec, stale-M ==========
        const int g = blockIdx.x;
        int bq[4], ln[4];
        const float* lg[4];
        #pragma unroll
        for (int q = 0; q < 4; ++q) {
            bq[q] = s_ord[4 * g + q];                 // sorted desc: ln[0] is max
            ln[q] = seq_lens[bq[q]];
            lg[q] = logits + (size_t)bq[q] * TT * KK;
        }

        // transposed exp(trans), padded rows (132 floats): row j holds E[0..127][j]
        for (int idx = tid; idx < KK * KK; idx += 128) {
            int i = idx >> 7, j = idx & 127;
            s_mat[j * 132 + i] = __expf(trans[idx]);
        }
        float a[4], M[4], ec[4];
        #pragma unroll
        for (int q = 0; q < 4; ++q) {
            a[q]  = lg[q][tid];
            M[q]  = __ldg(&lg[q][0]);
            ec[q] = (ln[q] > 1) ? __ldg(&lg[q][KK + tid]) : 0.f;
        }
        __syncthreads();

        const ulonglong2* mrow = (const ulonglong2*)(s_mat + tid * 132);
        int cur = 0;

        for (int t = 1; t < ln[0]; ++t) {
            const int tn = (t + 1 < TT) ? t + 1 : TT - 1;   // clamp: stay inside slab
            float nx[4];
            #pragma unroll
            for (int q = 0; q < 4; ++q) nx[q] = __ldg(&lg[q][tn * KK + tid]);
            #pragma unroll
            for (int q = 0; q < 4; ++q) s_p[cur * 512 + q * 128 + tid] = __expf(a[q] - M[q]);
            if (tid == 0) {
                #pragma unroll
                for (int q = 0; q < 4; ++q) s_M[cur * 4 + q] = a[q];
            }
            __syncthreads();
            float Mr[4];
            #pragma unroll
            for (int q = 0; q < 4; ++q) Mr[q] = s_M[cur * 4 + q];
            unsigned long long acc0[4] = {0,0,0,0}, acc1[4] = {0,0,0,0};
            const ulonglong2* pv = (const ulonglong2*)(s_p + cur * 512);
            #pragma unroll 4
            for (int k = 0; k < 32; ++k) {
                ulonglong2 mq = mrow[k];
                #pragma unroll
                for (int q = 0; q < 4; ++q) {
                    ulonglong2 pA = pv[q * 32 + k];   // ull2 = 4 floats; 128 floats = 32 ull2
                    FMA2(acc0[q], pA.x, mq.x);
                    FMA2(acc1[q], pA.y, mq.y);
                }
            }
            #pragma unroll
            for (int q = 0; q < 4; ++q) {
                unsigned long long s;
                ADD2(s, acc0[q], acc1[q]);
                unsigned lo, hi;
                asm("mov.b64 {%0, %1}, %2;" : "=r"(lo), "=r"(hi) : "l"(s));
                float dot = __uint_as_float(lo) + __uint_as_float(hi);
                if (t < ln[q]) a[q] = __logf(dot) + M[q] + ec[q];
                M[q]  = Mr[q];
                ec[q] = nx[q];
            }
            cur ^= 1;                                 // WAR guarded by next step's barrier
        }

        // ---- logZ + sequence score per batch, deterministic reductions ----
        #pragma unroll 1
        for (int pass = 0; pass < 4; ++pass) {
            float av = a[pass];
            int   b  = bq[pass];
            int   l2 = ln[pass];
            const float* lgb = lg[pass];
            unsigned wk = __reduce_max_sync(0xFFFFFFFFu, fkey(av));
            if (lane == 0) s_wkey[wid] = wk;
            __syncthreads();
            unsigned ak = max(max(s_wkey[0], s_wkey[1]), max(s_wkey[2], s_wkey[3]));
            float Mx = fval(ak);
            float e = __expf(av - Mx);
            #pragma unroll
            for (int m = 16; m > 0; m >>= 1) e += __shfl_xor_sync(0xFFFFFFFFu, e, m);
            if (lane == 0) s_red[wid] = e;

            const int* lab = labels + b * TT;
            float sc = 0.f;
            for (int t = tid; t < l2; t += 128) {
                int l = lab[t];
                sc += lgb[t * KK + l];
                if (t >= 1) sc += trans[lab[t - 1] * KK + l];
            }
            #pragma unroll
            for (int m = 16; m > 0; m >>= 1) sc += __shfl_xor_sync(0xFFFFFFFFu, sc, m);
            if (lane == 0) s_red[8 + wid] = sc;
            __syncthreads();
            if (tid == 0) {
                float S  = s_red[0] + s_red[1] + s_red[2] + s_red[3];
                float SC = s_red[8] + s_red[9] + s_red[10] + s_red[11];
                g_nll[b] = (__logf(S) + Mx) - SC;
            }
            __syncthreads();
        }
    }
}

// Deterministic final reduction: loss = sum_b nll[b]
extern "C" __global__ void crf_loss(float* __restrict__ out)
{
    __shared__ float s[BB];
    int tid = threadIdx.x;
    s[tid] = g_nll[tid];
    __syncthreads();
    for (int m = BB / 2; m > 0; m >>= 1) {
        if (tid < m) s[tid] += s[tid + m];
        __syncthreads();
    }
    if (tid == 0) out[0] = s[0];
}

extern "C" void kernel_launch(void* const* d_in, const int* in_sizes, int n_in,
                              void* d_out, int out_size)
{
    const float* logits   = (const float*)d_in[0];
    const int*   labels   = (const int*)d_in[1];
    const int*   seq_lens = (const int*)d_in[2];
    const float* trans    = (const float*)d_in[3];
    float* out = (float*)d_out;

    cudaFuncSetAttribute(crf_fwd, cudaFuncAttributeMaxDynamicSharedMemorySize, SMEM_BYTES);
    crf_fwd<<<320, 128, SMEM_BYTES>>>(logits, labels, seq_lens, trans, out);
    crf_loss<<<1, BB>>>(out);
}